// round 1
// baseline (speedup 1.0000x reference)
#include <cuda_runtime.h>
#include <cstdint>

#define HIDDEN 64
#define BATCH  4096
#define TSTEPS 9
#define DIM    512
#define GDIM   256                 // 4*HIDDEN
#define MROWS  (BATCH * TSTEPS)    // 36864

// Scratch for xg = x @ Wx + bias  (37.75 MB, static device global: allowed)
__device__ float g_xg[(size_t)MROWS * GDIM];

// ---------------------------------------------------------------------------
// helpers
// ---------------------------------------------------------------------------
__device__ __forceinline__ float f2tf(float f) {
    unsigned u;
    asm("cvt.rna.tf32.f32 %0, %1;" : "=r"(u) : "f"(f));
    return __uint_as_float(u);
}

__device__ __forceinline__ void mma_tf32(float c[4],
                                         unsigned a0, unsigned a1, unsigned a2, unsigned a3,
                                         unsigned b0, unsigned b1) {
    asm volatile(
        "mma.sync.aligned.m16n8k8.row.col.f32.tf32.tf32.f32 "
        "{%0,%1,%2,%3}, {%4,%5,%6,%7}, {%8,%9}, {%0,%1,%2,%3};"
        : "+f"(c[0]), "+f"(c[1]), "+f"(c[2]), "+f"(c[3])
        : "r"(a0), "r"(a1), "r"(a2), "r"(a3), "r"(b0), "r"(b1));
}

__device__ __forceinline__ float sigm(float x)  { return 1.0f / (1.0f + __expf(-x)); }
__device__ __forceinline__ float tanhx(float x) { return 1.0f - 2.0f / (__expf(2.0f * x) + 1.0f); }

// ---------------------------------------------------------------------------
// Kernel 1: xg[36864,256] = x2d[36864,512] @ Wx[512,256] + bias   (tf32 mma)
// Block tile 128x128, BK=32, 8 warps (4m x 2n), warp tile 32x64.
// ---------------------------------------------------------------------------
#define BM 128
#define BN 128
#define BK 32

__global__ void __launch_bounds__(256, 1)
gemm_xg(const float* __restrict__ x, const float* __restrict__ w,
        const float* __restrict__ bias) {
    __shared__ float As[BM][BK + 4];   // pad 4 -> conflict-free frag loads
    __shared__ float Bs[BK][BN + 8];   // pad 8 -> conflict-free frag loads

    const int tid    = threadIdx.x;
    const int bm     = blockIdx.y * BM;
    const int bn     = blockIdx.x * BN;
    const int warpid = tid >> 5, lane = tid & 31;
    const int wm  = warpid & 3, wn  = warpid >> 2;
    const int grp = lane >> 2,  tig = lane & 3;

    // global->reg staging coords
    const int ra = tid >> 3,  ca = (tid & 7)  * 4;  // A: 128 rows x 8 float4
    const int rb = tid >> 5,  cb = (tid & 31) * 4;  // B: 32 rows x 32 float4

    float4 av[4], bv[4];
    float  acc[2][8][4];
    #pragma unroll
    for (int i = 0; i < 2; i++)
        #pragma unroll
        for (int j = 0; j < 8; j++)
            #pragma unroll
            for (int k = 0; k < 4; k++) acc[i][j][k] = 0.0f;

    auto LOAD = [&](int kk) {
        #pragma unroll
        for (int i = 0; i < 4; i++) {
            av[i] = *(const float4*)(x + (size_t)(bm + ra + i * 32) * DIM + kk + ca);
            bv[i] = *(const float4*)(w + (size_t)(kk + rb + i * 8) * GDIM + bn + cb);
        }
    };
    auto STORE = [&]() {
        #pragma unroll
        for (int i = 0; i < 4; i++) {
            As[ra + i * 32][ca + 0] = f2tf(av[i].x);
            As[ra + i * 32][ca + 1] = f2tf(av[i].y);
            As[ra + i * 32][ca + 2] = f2tf(av[i].z);
            As[ra + i * 32][ca + 3] = f2tf(av[i].w);
            Bs[rb + i * 8][cb + 0]  = f2tf(bv[i].x);
            Bs[rb + i * 8][cb + 1]  = f2tf(bv[i].y);
            Bs[rb + i * 8][cb + 2]  = f2tf(bv[i].z);
            Bs[rb + i * 8][cb + 3]  = f2tf(bv[i].w);
        }
    };
    auto COMPUTE = [&]() {
        #pragma unroll
        for (int ks = 0; ks < 4; ks++) {
            const int kb = ks * 8;
            unsigned af[2][4];
            #pragma unroll
            for (int mi = 0; mi < 2; mi++) {
                const int r0 = wm * 32 + mi * 16;
                af[mi][0] = __float_as_uint(As[r0 + grp][kb + tig]);
                af[mi][1] = __float_as_uint(As[r0 + grp + 8][kb + tig]);
                af[mi][2] = __float_as_uint(As[r0 + grp][kb + tig + 4]);
                af[mi][3] = __float_as_uint(As[r0 + grp + 8][kb + tig + 4]);
            }
            #pragma unroll
            for (int ni = 0; ni < 8; ni++) {
                const int c0 = wn * 64 + ni * 8;
                unsigned b0 = __float_as_uint(Bs[kb + tig][c0 + grp]);
                unsigned b1 = __float_as_uint(Bs[kb + tig + 4][c0 + grp]);
                #pragma unroll
                for (int mi = 0; mi < 2; mi++)
                    mma_tf32(acc[mi][ni], af[mi][0], af[mi][1], af[mi][2], af[mi][3], b0, b1);
            }
        }
    };

    LOAD(0);
    STORE();
    __syncthreads();
    #pragma unroll 1
    for (int kt = 1; kt < DIM / BK; kt++) {
        LOAD(kt * BK);
        COMPUTE();
        __syncthreads();
        STORE();
        __syncthreads();
    }
    COMPUTE();

    // epilogue: natural layout xg[row][col] + bias
    #pragma unroll
    for (int mi = 0; mi < 2; mi++) {
        #pragma unroll
        for (int ni = 0; ni < 8; ni++) {
            const int row = bm + wm * 32 + mi * 16 + grp;
            const int col = bn + wn * 64 + ni * 8 + tig * 2;
            const float bb0 = bias[col], bb1 = bias[col + 1];
            g_xg[(size_t)row * GDIM + col]           = acc[mi][ni][0] + bb0;
            g_xg[(size_t)row * GDIM + col + 1]       = acc[mi][ni][1] + bb1;
            g_xg[(size_t)(row + 8) * GDIM + col]     = acc[mi][ni][2] + bb0;
            g_xg[(size_t)(row + 8) * GDIM + col + 1] = acc[mi][ni][3] + bb1;
        }
    }
}

// ---------------------------------------------------------------------------
// Kernel 2: sequential LSTM scan.
// Block = 256 threads, handles NB=32 batches. Thread (h = tid&63, bq = tid>>6)
// owns gate-quad {i,j,f,o}[h] for 8 batches -> each Wh read (LDS.128) feeds
// 32 FMAs (weight reuse across batches => FFMA-bound, not LDS-BW-bound).
// Wh reordered in smem: Whr[k][h*4+q] = Wh[k][q*64+h]. h double-buffered with
// row stride 33 (odd) -> conflict-free scattered writes, broadcast reads.
// ---------------------------------------------------------------------------
__global__ void __launch_bounds__(256, 1)
lstm_scan(const float* __restrict__ w, float* __restrict__ out) {
    extern __shared__ float sm[];
    float* Whr = sm;               // [64][256]
    float* hb  = sm + 64 * 256;    // [2][64][33]

    const int tid   = threadIdx.x;
    const int h     = tid & 63;
    const int bq    = tid >> 6;                    // 0..3
    const int bbase = blockIdx.x * 32 + bq * 8;    // 8 batches per thread

    // load + reorder Wh (rows 512..575 of kernel)
    for (int idx = tid; idx < 64 * 256; idx += 256) {
        const int k = idx >> 8, col = idx & 255;
        const int q = col >> 6, hh = col & 63;
        Whr[k * 256 + hh * 4 + q] = w[(size_t)(DIM + k) * GDIM + col];
    }
    for (int idx = tid; idx < 64 * 33; idx += 256) hb[idx] = 0.0f;
    __syncthreads();

    float c[8];
    #pragma unroll
    for (int j = 0; j < 8; j++) c[j] = 0.0f;

    int p = 0;
    for (int t = 0; t < TSTEPS; t++) {
        // start from xg (coalesced LDG: lanes span consecutive h)
        float acc[8][4];
        #pragma unroll
        for (int j = 0; j < 8; j++) {
            const size_t ro = ((size_t)(bbase + j) * TSTEPS + t) * GDIM;
            #pragma unroll
            for (int q = 0; q < 4; q++) acc[j][q] = g_xg[ro + q * 64 + h];
        }

        // gates += h @ Wh
        const float* hp = hb + p * 64 * 33 + bq * 8;
        #pragma unroll 4
        for (int k = 0; k < 64; k++) {
            const float4 w4 = *(const float4*)(Whr + k * 256 + h * 4);
            #pragma unroll
            for (int j = 0; j < 8; j++) {
                const float hv = hp[k * 33 + j];   // warp-broadcast LDS
                acc[j][0] += w4.x * hv;
                acc[j][1] += w4.y * hv;
                acc[j][2] += w4.z * hv;
                acc[j][3] += w4.w * hv;
            }
        }

        // activations + state update
        float* hw = hb + (p ^ 1) * 64 * 33 + h * 33 + bq * 8;
        #pragma unroll
        for (int j = 0; j < 8; j++) {
            const float ig = sigm(acc[j][0]);
            const float jg = tanhx(acc[j][1]);
            const float fg = sigm(acc[j][2] + 1.0f);   // FORGET_BIAS
            const float og = sigm(acc[j][3]);
            const float cn = fg * c[j] + ig * jg;
            c[j] = cn;
            const float hn = og * tanhx(cn);
            hw[j] = hn;                                // conflict-free (stride 33)
            out[((size_t)(bbase + j) * TSTEPS + t) * HIDDEN + h] = hn;
        }
        __syncthreads();
        p ^= 1;
    }
}

// ---------------------------------------------------------------------------
extern "C" void kernel_launch(void* const* d_in, const int* in_sizes, int n_in,
                              void* d_out, int out_size) {
    const float* x    = (const float*)d_in[0];
    const float* w    = (const float*)d_in[1];
    const float* bias = (const float*)d_in[2];
    float* out        = (float*)d_out;
    (void)in_sizes; (void)n_in; (void)out_size;

    dim3 g1(GDIM / BN, MROWS / BM);   // (2, 288)
    gemm_xg<<<g1, 256>>>(x, w, bias);

    const int shmem = (64 * 256 + 2 * 64 * 33) * (int)sizeof(float);  // 82432 B
    cudaFuncSetAttribute(lstm_scan, cudaFuncAttributeMaxDynamicSharedMemorySize, shmem);
    lstm_scan<<<128, 256, shmem>>>(w, out);
}

// round 2
// speedup vs baseline: 1.0438x; 1.0438x over previous
#include <cuda_runtime.h>
#include <cstdint>

#define HIDDEN 64
#define BATCH  4096
#define TSTEPS 9
#define DIM    512
#define GDIM   256                 // 4*HIDDEN
#define MROWS  (BATCH * TSTEPS)    // 36864

// Scratch: xg = x @ Wx + bias  (37.75 MB) and tf32-rounded Wx copy (512 KB)
__device__ float g_xg[(size_t)MROWS * GDIM];
__device__ float g_wx[(size_t)DIM * GDIM];

// ---------------------------------------------------------------------------
// helpers
// ---------------------------------------------------------------------------
__device__ __forceinline__ unsigned f2tf_u(float f) {
    unsigned u;
    asm("cvt.rna.tf32.f32 %0, %1;" : "=r"(u) : "f"(f));
    return u;
}

__device__ __forceinline__ void mma_tf32(float c[4],
                                         unsigned a0, unsigned a1, unsigned a2, unsigned a3,
                                         unsigned b0, unsigned b1) {
    asm volatile(
        "mma.sync.aligned.m16n8k8.row.col.f32.tf32.tf32.f32 "
        "{%0,%1,%2,%3}, {%4,%5,%6,%7}, {%8,%9}, {%0,%1,%2,%3};"
        : "+f"(c[0]), "+f"(c[1]), "+f"(c[2]), "+f"(c[3])
        : "r"(a0), "r"(a1), "r"(a2), "r"(a3), "r"(b0), "r"(b1));
}

__device__ __forceinline__ void cpa16(void* dst, const void* src) {
    unsigned d = (unsigned)__cvta_generic_to_shared(dst);
    asm volatile("cp.async.cg.shared.global [%0], [%1], 16;" :: "r"(d), "l"(src));
}
__device__ __forceinline__ void cpa_commit() { asm volatile("cp.async.commit_group;"); }
__device__ __forceinline__ void cpa_wait2()  { asm volatile("cp.async.wait_group 2;"); }

__device__ __forceinline__ float sigm(float x)  { return 1.0f / (1.0f + __expf(-x)); }
__device__ __forceinline__ float tanhx(float x) { return 1.0f - 2.0f / (__expf(2.0f * x) + 1.0f); }

// packed f32x2 fma (sm_103a FFMA2 — only reachable via PTX)
__device__ __forceinline__ void fma2(unsigned long long& acc,
                                     unsigned long long a, unsigned long long b) {
    asm("fma.rn.f32x2 %0, %1, %2, %0;" : "+l"(acc) : "l"(a), "l"(b));
}

// ---------------------------------------------------------------------------
// Kernel 0: round Wx (first 512 rows of kernel) to tf32 once.
// ---------------------------------------------------------------------------
__global__ void wconv(const float* __restrict__ w) {
    int i = blockIdx.x * 256 + threadIdx.x;     // grid covers 512*256
    g_wx[i] = __uint_as_float(f2tf_u(w[i]));
}

// ---------------------------------------------------------------------------
// Kernel 1: xg[36864,256] = x[36864,512] @ Wx[512,256] + bias  (tf32 mma)
// BM=128, BN=256 (full width -> x read once), BK=16, 4-stage cp.async.
// 512 threads = 16 warps (4m x 4n), warp tile 32x64.
// ---------------------------------------------------------------------------
#define BMg 128
#define BKg 16
#define AST 20     // As row stride (pad 4): conflict-free frag loads
#define BST 264    // Bs row stride (pad 8)
#define GEMM_SMEM ((4 * BMg * AST + 4 * BKg * BST) * 4)   // 108544 B

__global__ void __launch_bounds__(512, 1)
gemm_xg(const float* __restrict__ x, const float* __restrict__ bias) {
    extern __shared__ float sm[];
    float* As = sm;                   // [4][128][AST]
    float* Bs = sm + 4 * BMg * AST;   // [4][16][BST]

    const int tid = threadIdx.x;
    const int bm  = blockIdx.x * BMg;
    const int warpid = tid >> 5, lane = tid & 31;
    const int wm = warpid & 3, wn = warpid >> 2;
    const int grp = lane >> 2, tig = lane & 3;

    // staging coords
    const int ra = tid >> 2, ca = (tid & 3) * 4;      // A: one 16B per thread
    const int rb0 = tid >> 6, cb0 = (tid & 63) * 4;   // B: two 16B per thread
    const int rb1 = (tid + 512) >> 6, cb1 = cb0;

    float acc[2][8][4];
    #pragma unroll
    for (int i = 0; i < 2; i++)
        #pragma unroll
        for (int j = 0; j < 8; j++)
            #pragma unroll
            for (int k = 0; k < 4; k++) acc[i][j][k] = 0.0f;

    auto ISSUE = [&](int stage, int kt) {
        float* a = As + stage * BMg * AST;
        float* b = Bs + stage * BKg * BST;
        cpa16(a + ra * AST + ca, x + (size_t)(bm + ra) * DIM + kt * BKg + ca);
        cpa16(b + rb0 * BST + cb0, g_wx + (size_t)(kt * BKg + rb0) * GDIM + cb0);
        cpa16(b + rb1 * BST + cb1, g_wx + (size_t)(kt * BKg + rb1) * GDIM + cb1);
        cpa_commit();
    };

    ISSUE(0, 0); ISSUE(1, 1); ISSUE(2, 2);

    #pragma unroll 1
    for (int kt = 0; kt < DIM / BKg; kt++) {
        cpa_wait2();
        __syncthreads();
        if (kt + 3 < DIM / BKg) ISSUE((kt + 3) & 3, kt + 3);

        const float* a = As + (kt & 3) * BMg * AST;
        const float* b = Bs + (kt & 3) * BKg * BST;
        #pragma unroll
        for (int ks = 0; ks < 2; ks++) {
            const int kb = ks * 8;
            unsigned af[2][4];
            #pragma unroll
            for (int mi = 0; mi < 2; mi++) {
                const int r0 = wm * 32 + mi * 16;
                af[mi][0] = f2tf_u(a[(r0 + grp) * AST + kb + tig]);
                af[mi][1] = f2tf_u(a[(r0 + grp + 8) * AST + kb + tig]);
                af[mi][2] = f2tf_u(a[(r0 + grp) * AST + kb + tig + 4]);
                af[mi][3] = f2tf_u(a[(r0 + grp + 8) * AST + kb + tig + 4]);
            }
            #pragma unroll
            for (int ni = 0; ni < 8; ni++) {
                const int c0 = wn * 64 + ni * 8;
                unsigned b0 = __float_as_uint(b[(kb + tig) * BST + c0 + grp]);
                unsigned b1 = __float_as_uint(b[(kb + tig + 4) * BST + c0 + grp]);
                #pragma unroll
                for (int mi = 0; mi < 2; mi++)
                    mma_tf32(acc[mi][ni], af[mi][0], af[mi][1], af[mi][2], af[mi][3], b0, b1);
            }
        }
    }

    // epilogue: natural layout xg[row][col] + bias
    #pragma unroll
    for (int mi = 0; mi < 2; mi++) {
        #pragma unroll
        for (int ni = 0; ni < 8; ni++) {
            const int row = bm + wm * 32 + mi * 16 + grp;
            const int col = wn * 64 + ni * 8 + tig * 2;
            const float bb0 = bias[col], bb1 = bias[col + 1];
            g_xg[(size_t)row * GDIM + col]           = acc[mi][ni][0] + bb0;
            g_xg[(size_t)row * GDIM + col + 1]       = acc[mi][ni][1] + bb1;
            g_xg[(size_t)(row + 8) * GDIM + col]     = acc[mi][ni][2] + bb0;
            g_xg[(size_t)(row + 8) * GDIM + col + 1] = acc[mi][ni][3] + bb1;
        }
    }
}

// ---------------------------------------------------------------------------
// Kernel 2: LSTM scan with packed f32x2 FFMA2.
// Block = 256 threads, 32 batches. Thread (h = tid&63, bq = tid>>6) owns the
// gate-quad {i,j,f,o}[h] for 8 batches, gates packed as (i,j)/(f,o) in 64-bit.
// Wh stored in smem pre-permuted so one LDS.128 gives both packed weight
// pairs; h stored DUPLICATED as {h,h} 64-bit words so a single LDS.64
// broadcast feeds both fma2 ops (no pack movs in the hot loop).
// Step 0 has h=0 -> the 64-deep k-loop is skipped entirely.
// ---------------------------------------------------------------------------
#define HVV 33                   // 64-bit stride per hidden row (odd -> 2-way max)
#define SCAN_SMEM (64 * 256 * 4 + 2 * 64 * HVV * 8)   // 99328 B

__global__ void __launch_bounds__(256, 1)
lstm_scan(const float* __restrict__ w, float* __restrict__ out) {
    extern __shared__ float sm[];
    float* Whr = sm;                                                // [64][256]
    unsigned long long* hvv = (unsigned long long*)(sm + 64 * 256); // [2][64][HVV]

    const int tid   = threadIdx.x;
    const int h     = tid & 63;
    const int bq    = tid >> 6;                    // 0..3
    const int bbase = blockIdx.x * 32 + bq * 8;

    // load + permute Wh: Whr[k][h*4+q] = Wh[k][q*64+h]
    for (int idx = tid; idx < 64 * 256; idx += 256) {
        const int k = idx >> 8, col = idx & 255;
        const int q = col >> 6, hh = col & 63;
        Whr[k * 256 + hh * 4 + q] = w[(size_t)(DIM + k) * GDIM + col];
    }
    __syncthreads();

    float c[8];
    #pragma unroll
    for (int j = 0; j < 8; j++) c[j] = 0.0f;

    unsigned long long acc01[8], acc23[8];

    for (int t = 0; t < TSTEPS; t++) {
        // gates = xg  (coalesced: lanes span consecutive h), packed
        #pragma unroll
        for (int j = 0; j < 8; j++) {
            const size_t ro = ((size_t)(bbase + j) * TSTEPS + t) * GDIM;
            const float gi = g_xg[ro + h];
            const float gj = g_xg[ro + 64 + h];
            const float gf = g_xg[ro + 128 + h];
            const float go = g_xg[ro + 192 + h];
            asm("mov.b64 %0, {%1,%2};" : "=l"(acc01[j]) : "f"(gi), "f"(gj));
            asm("mov.b64 %0, {%1,%2};" : "=l"(acc23[j]) : "f"(gf), "f"(go));
        }

        if (t > 0) {
            // gates += h_{t-1} @ Wh   (packed FFMA2)
            const unsigned long long* hp = hvv + ((t - 1) & 1) * 64 * HVV + bq * 8;
            #pragma unroll 4
            for (int k = 0; k < 64; k++) {
                const ulonglong2 wv =
                    *(const ulonglong2*)(Whr + k * 256 + h * 4);   // LDS.128
                #pragma unroll
                for (int j = 0; j < 8; j++) {
                    const unsigned long long hk = hp[k * HVV + j]; // LDS.64 bcast {h,h}
                    fma2(acc01[j], wv.x, hk);
                    fma2(acc23[j], wv.y, hk);
                }
            }
        }

        // activations + state update; write duplicated {h,h} for next step
        unsigned long long* hw = hvv + (t & 1) * 64 * HVV + h * HVV + bq * 8;
        #pragma unroll
        for (int j = 0; j < 8; j++) {
            float gi, gj, gf, go;
            asm("mov.b64 {%0,%1}, %2;" : "=f"(gi), "=f"(gj) : "l"(acc01[j]));
            asm("mov.b64 {%0,%1}, %2;" : "=f"(gf), "=f"(go) : "l"(acc23[j]));
            const float ig = sigm(gi);
            const float jg = tanhx(gj);
            const float fg = sigm(gf + 1.0f);          // FORGET_BIAS
            const float og = sigm(go);
            const float cn = fg * c[j] + ig * jg;
            c[j] = cn;
            const float hn = og * tanhx(cn);
            unsigned long long hd;
            asm("mov.b64 %0, {%1,%1};" : "=l"(hd) : "f"(hn));
            hw[j] = hd;
            out[((size_t)(bbase + j) * TSTEPS + t) * HIDDEN + h] = hn;
        }
        __syncthreads();
    }
}

// ---------------------------------------------------------------------------
extern "C" void kernel_launch(void* const* d_in, const int* in_sizes, int n_in,
                              void* d_out, int out_size) {
    const float* x    = (const float*)d_in[0];
    const float* w    = (const float*)d_in[1];
    const float* bias = (const float*)d_in[2];
    float* out        = (float*)d_out;
    (void)in_sizes; (void)n_in; (void)out_size;

    wconv<<<DIM * GDIM / 256, 256>>>(w);

    cudaFuncSetAttribute(gemm_xg, cudaFuncAttributeMaxDynamicSharedMemorySize, GEMM_SMEM);
    gemm_xg<<<MROWS / BMg, 512, GEMM_SMEM>>>(x, bias);

    cudaFuncSetAttribute(lstm_scan, cudaFuncAttributeMaxDynamicSharedMemorySize, SCAN_SMEM);
    lstm_scan<<<BATCH / 32, 256, SCAN_SMEM>>>(w, out);
}

// round 9
// speedup vs baseline: 1.3161x; 1.2608x over previous
#include <cuda_runtime.h>
#include <cuda_fp16.h>
#include <cstdint>

#define HIDDEN 64
#define BATCH  4096
#define TSTEPS 9
#define DIM    512
#define GDIM   256                 // 4*HIDDEN
#define MROWS  (BATCH * TSTEPS)    // 36864

// Scratch (static device globals: allocation-guard-safe)
__device__ float  g_xg[(size_t)MROWS * GDIM];   // xg = x @ Wx + bias
__device__ __half g_wxTh[(size_t)GDIM * DIM];   // Wx^T [256][512] in fp16

// ---------------------------------------------------------------------------
// helpers
// ---------------------------------------------------------------------------
__device__ __forceinline__ void mma_f16(float c[4],
                                        unsigned a0, unsigned a1, unsigned a2, unsigned a3,
                                        unsigned b0, unsigned b1) {
    asm volatile(
        "mma.sync.aligned.m16n8k16.row.col.f32.f16.f16.f32 "
        "{%0,%1,%2,%3}, {%4,%5,%6,%7}, {%8,%9}, {%0,%1,%2,%3};"
        : "+f"(c[0]), "+f"(c[1]), "+f"(c[2]), "+f"(c[3])
        : "r"(a0), "r"(a1), "r"(a2), "r"(a3), "r"(b0), "r"(b1));
}

__device__ __forceinline__ unsigned pack_h2(float lo, float hi) {
    unsigned r;   // cvt.rn.f16x2.f32 d,a,b : a -> high half, b -> low half
    asm("cvt.rn.f16x2.f32 %0, %1, %2;" : "=r"(r) : "f"(hi), "f"(lo));
    return r;
}

__device__ __forceinline__ float sigm(float x)  { return 1.0f / (1.0f + __expf(-x)); }
__device__ __forceinline__ float tanhx(float x) { return 1.0f - 2.0f / (__expf(2.0f * x) + 1.0f); }
__device__ __forceinline__ void fma2(unsigned long long& acc,
                                     unsigned long long a, unsigned long long b) {
    asm("fma.rn.f32x2 %0, %1, %2, %0;" : "+l"(acc) : "l"(a), "l"(b));
}

// ---------------------------------------------------------------------------
// Kernel 0: Wx^T in fp16:  g_wxTh[n][k] = half(Wx[k][n])
// ---------------------------------------------------------------------------
__global__ void wtrans(const float* __restrict__ w) {
    const int idx = blockIdx.x * 256 + threadIdx.x;   // over 256*512
    const int n = idx >> 9, k = idx & 511;
    g_wxTh[idx] = __float2half(w[(size_t)k * GDIM + n]);
}

// ---------------------------------------------------------------------------
// Kernel 1: xg[36864,256] = x @ Wx + bias  (fp16 mma m16n8k16, fp32 accum)
// BM=128, BN=256 (x read once), BK=32. 512 threads = 16 warps (4m x 4n),
// warp tile 32x64. Reg-double-buffered staging: LDG(+cvt for A) -> STS.
// Smem rows stored as half2, row stride KST=20 (16 used) -> conflict-free.
// ---------------------------------------------------------------------------
#define BMg 128
#define BNg 256
#define BKg 32
#define KST 20                                   // half2 stride per row
#define GEMM_SMEM ((BMg + BNg) * KST * 4)        // 30720 B (single stage)

__global__ void __launch_bounds__(512, 1)
gemm_xg(const float* __restrict__ x, const float* __restrict__ bias) {
    extern __shared__ unsigned sm[];
    unsigned* As2 = sm;                 // [128][KST] half2
    unsigned* Bs2 = sm + BMg * KST;     // [256][KST] half2

    const int tid = threadIdx.x;
    const int bm  = blockIdx.x * BMg;
    const int wid = tid >> 5, lane = tid & 31;
    const int wm = wid & 3, wn = wid >> 2;
    const int grp = lane >> 2, tig = lane & 3;

    // staging coords
    const int ra = tid >> 2, ca = (tid & 3) * 8;   // A: 8 floats / thread
    const int rb = tid >> 1, cb = (tid & 1) * 8;   // B: 8 half2 (16 halves) / thread

    const float* asrc = x + (size_t)(bm + ra) * DIM + ca;
    const __half* bsrc = g_wxTh + (size_t)rb * DIM + cb * 2;

    float4 av0, av1;
    uint4  bv0, bv1;

    auto LOAD = [&](int kt) {
        av0 = *(const float4*)(asrc + kt * BKg);
        av1 = *(const float4*)(asrc + kt * BKg + 4);
        bv0 = *(const uint4*)(bsrc + kt * BKg);       // halves 0..7
        bv1 = *(const uint4*)(bsrc + kt * BKg + 8);   // halves 8..15
    };
    auto STORE = [&]() {
        uint4 ah;
        ah.x = pack_h2(av0.x, av0.y);
        ah.y = pack_h2(av0.z, av0.w);
        ah.z = pack_h2(av1.x, av1.y);
        ah.w = pack_h2(av1.z, av1.w);
        *(uint4*)(As2 + ra * KST + ca / 2)   = ah;
        *(uint4*)(Bs2 + rb * KST + cb)       = bv0;   // half2 idx cb..cb+3
        *(uint4*)(Bs2 + rb * KST + cb + 4)   = bv1;   // half2 idx cb+4..cb+7
    };

    float acc[2][8][4];
    #pragma unroll
    for (int i = 0; i < 2; i++)
        #pragma unroll
        for (int j = 0; j < 8; j++)
            #pragma unroll
            for (int k = 0; k < 4; k++) acc[i][j][k] = 0.0f;

    auto COMPUTE = [&]() {
        #pragma unroll
        for (int ks = 0; ks < 2; ks++) {
            const int kb = ks * 8;
            unsigned af[2][4];
            #pragma unroll
            for (int mi = 0; mi < 2; mi++) {
                const int r0 = wm * 32 + mi * 16;
                af[mi][0] = As2[(r0 + grp) * KST + kb + tig];
                af[mi][1] = As2[(r0 + grp + 8) * KST + kb + tig];
                af[mi][2] = As2[(r0 + grp) * KST + kb + tig + 4];
                af[mi][3] = As2[(r0 + grp + 8) * KST + kb + tig + 4];
            }
            #pragma unroll
            for (int ni = 0; ni < 8; ni++) {
                const int c0 = wn * 64 + ni * 8;
                unsigned b0 = Bs2[(c0 + grp) * KST + kb + tig];
                unsigned b1 = Bs2[(c0 + grp) * KST + kb + tig + 4];
                #pragma unroll
                for (int mi = 0; mi < 2; mi++)
                    mma_f16(acc[mi][ni], af[mi][0], af[mi][1], af[mi][2], af[mi][3], b0, b1);
            }
        }
    };

    LOAD(0);
    STORE();
    __syncthreads();
    #pragma unroll 1
    for (int kt = 1; kt < DIM / BKg; kt++) {
        LOAD(kt);            // LDG latency hides under COMPUTE
        COMPUTE();
        __syncthreads();
        STORE();
        __syncthreads();
    }
    COMPUTE();

    // epilogue: natural layout xg[row][col] + bias
    #pragma unroll
    for (int mi = 0; mi < 2; mi++) {
        #pragma unroll
        for (int ni = 0; ni < 8; ni++) {
            const int row = bm + wm * 32 + mi * 16 + grp;
            const int col = wn * 64 + ni * 8 + tig * 2;
            const float bb0 = bias[col], bb1 = bias[col + 1];
            g_xg[(size_t)row * GDIM + col]           = acc[mi][ni][0] + bb0;
            g_xg[(size_t)row * GDIM + col + 1]       = acc[mi][ni][1] + bb1;
            g_xg[(size_t)(row + 8) * GDIM + col]     = acc[mi][ni][2] + bb0;
            g_xg[(size_t)(row + 8) * GDIM + col + 1] = acc[mi][ni][3] + bb1;
        }
    }
}

// ---------------------------------------------------------------------------
// Kernel 2: LSTM scan, packed f32x2 FFMA2. 256 CTAs x 16 batches (4/thread),
// smem 83 KB -> 2 CTAs/SM. Thread (h=tid&63, bq=tid>>6) owns gate quad
// {i,j,f,o}[h] for 4 batches; h stored duplicated {h,h} so one LDS.64
// broadcast feeds both FFMA2s. t=0 skips the k-loop (h0 = 0).
// ---------------------------------------------------------------------------
#define NBATCH 16
#define HV 17                    // 64-bit stride per hidden row (odd)
#define SCAN_SMEM (64 * 256 * 4 + 2 * 64 * HV * 8)   // 82944 B

__global__ void __launch_bounds__(256, 2)
lstm_scan(const float* __restrict__ w, float* __restrict__ out) {
    extern __shared__ float sms[];
    float* Whr = sms;                                                // [64][256]
    unsigned long long* hvv = (unsigned long long*)(sms + 64 * 256); // [2][64][HV]

    const int tid   = threadIdx.x;
    const int h     = tid & 63;
    const int bq    = tid >> 6;                    // 0..3
    const int bbase = blockIdx.x * NBATCH + bq * 4;

    // load + permute Wh: Whr[k][h*4+q] = Wh[k][q*64+h]
    for (int idx = tid; idx < 64 * 256; idx += 256) {
        const int k = idx >> 8, col = idx & 255;
        const int q = col >> 6, hh = col & 63;
        Whr[k * 256 + hh * 4 + q] = w[(size_t)(DIM + k) * GDIM + col];
    }
    __syncthreads();

    float c[4];
    #pragma unroll
    for (int j = 0; j < 4; j++) c[j] = 0.0f;

    unsigned long long acc01[4], acc23[4];

    for (int t = 0; t < TSTEPS; t++) {
        #pragma unroll
        for (int j = 0; j < 4; j++) {
            const size_t ro = ((size_t)(bbase + j) * TSTEPS + t) * GDIM;
            const float gi = g_xg[ro + h];
            const float gj = g_xg[ro + 64 + h];
            const float gf = g_xg[ro + 128 + h];
            const float go = g_xg[ro + 192 + h];
            asm("mov.b64 %0, {%1,%2};" : "=l"(acc01[j]) : "f"(gi), "f"(gj));
            asm("mov.b64 %0, {%1,%2};" : "=l"(acc23[j]) : "f"(gf), "f"(go));
        }

        if (t > 0) {
            const unsigned long long* hp = hvv + ((t - 1) & 1) * 64 * HV + bq * 4;
            #pragma unroll 4
            for (int k = 0; k < 64; k++) {
                const ulonglong2 wv = *(const ulonglong2*)(Whr + k * 256 + h * 4);
                #pragma unroll
                for (int j = 0; j < 4; j++) {
                    const unsigned long long hk = hp[k * HV + j];   // broadcast
                    fma2(acc01[j], wv.x, hk);
                    fma2(acc23[j], wv.y, hk);
                }
            }
        }

        unsigned long long* hw = hvv + (t & 1) * 64 * HV + h * HV + bq * 4;
        #pragma unroll
        for (int j = 0; j < 4; j++) {
            float gi, gj, gf, go;
            asm("mov.b64 {%0,%1}, %2;" : "=f"(gi), "=f"(gj) : "l"(acc01[j]));
            asm("mov.b64 {%0,%1}, %2;" : "=f"(gf), "=f"(go) : "l"(acc23[j]));
            const float ig = sigm(gi);
            const float jg = tanhx(gj);
            const float fg = sigm(gf + 1.0f);          // FORGET_BIAS
            const float og = sigm(go);
            const float cn = fg * c[j] + ig * jg;
            c[j] = cn;
            const float hn = og * tanhx(cn);
            unsigned long long hd;
            asm("mov.b64 %0, {%1,%1};" : "=l"(hd) : "f"(hn));
            hw[j] = hd;
            out[((size_t)(bbase + j) * TSTEPS + t) * HIDDEN + h] = hn;
        }
        __syncthreads();
    }
}

// ---------------------------------------------------------------------------
extern "C" void kernel_launch(void* const* d_in, const int* in_sizes, int n_in,
                              void* d_out, int out_size) {
    const float* x    = (const float*)d_in[0];
    const float* w    = (const float*)d_in[1];
    const float* bias = (const float*)d_in[2];
    float* out        = (float*)d_out;
    (void)in_sizes; (void)n_in; (void)out_size;

    wtrans<<<GDIM * DIM / 256, 256>>>(w);

    cudaFuncSetAttribute(gemm_xg, cudaFuncAttributeMaxDynamicSharedMemorySize, GEMM_SMEM);
    gemm_xg<<<MROWS / BMg, 512, GEMM_SMEM>>>(x, bias);

    cudaFuncSetAttribute(lstm_scan, cudaFuncAttributeMaxDynamicSharedMemorySize, SCAN_SMEM);
    lstm_scan<<<BATCH / NBATCH, 256, SCAN_SMEM>>>(w, out);
}